// round 8
// baseline (speedup 1.0000x reference)
#include <cuda_runtime.h>
#include <cstdint>

#define AA 512      // attention length
#define OUTS 512    // out_size
#define HH 512
#define WW 512
#define CC 3
#define NMAX 32

// scratch (allocation-free rule: device globals)
__device__ float g_px[NMAX * OUTS];
__device__ float g_py[NMAX * OUTS];

__device__ __forceinline__ float warpSum(float v) {
    #pragma unroll
    for (int o = 16; o; o >>= 1) v += __shfl_xor_sync(0xffffffffu, v, o);
    return v;
}
__device__ __forceinline__ float warpMax(float v) {
    #pragma unroll
    for (int o = 16; o; o >>= 1) v = fmaxf(v, __shfl_xor_sync(0xffffffffu, v, o));
    return v;
}

// fused block reductions for two values (512 threads), one barrier pair each
__device__ void blockSum2(float a, float b, volatile float* sbuf, float* ra, float* rb) {
    int lane = threadIdx.x & 31, w = threadIdx.x >> 5;
    a = warpSum(a); b = warpSum(b);
    if (lane == 0) { sbuf[w] = a; sbuf[32 + w] = b; }
    __syncthreads();
    if (w == 0) {
        float x = (lane < 16) ? sbuf[lane] : 0.f;
        float y = (lane < 16) ? sbuf[32 + lane] : 0.f;
        x = warpSum(x); y = warpSum(y);
        if (lane == 0) { sbuf[0] = x; sbuf[32] = y; }
    }
    __syncthreads();
    *ra = sbuf[0]; *rb = sbuf[32];
    __syncthreads();
}

__device__ void blockMax2(float a, float b, volatile float* sbuf, float* ra, float* rb) {
    int lane = threadIdx.x & 31, w = threadIdx.x >> 5;
    a = warpMax(a); b = warpMax(b);
    if (lane == 0) { sbuf[w] = a; sbuf[32 + w] = b; }
    __syncthreads();
    if (w == 0) {
        float x = (lane < 16) ? sbuf[lane] : -3.4e38f;
        float y = (lane < 16) ? sbuf[32 + lane] : -3.4e38f;
        x = warpMax(x); y = warpMax(y);
        if (lane == 0) { sbuf[0] = x; sbuf[32] = y; }
    }
    __syncthreads();
    *ra = sbuf[0]; *rb = sbuf[32];
    __syncthreads();
}

// fused inclusive block scan of two 512-value sequences -> outa[tid], outb[tid]
__device__ void blockScan2(float a, float b, float* outa, float* outb, volatile float* sbuf) {
    int lane = threadIdx.x & 31, w = threadIdx.x >> 5;
    float sa = a, sb = b;
    #pragma unroll
    for (int o = 1; o < 32; o <<= 1) {
        float ta = __shfl_up_sync(0xffffffffu, sa, o);
        float tb = __shfl_up_sync(0xffffffffu, sb, o);
        if (lane >= o) { sa += ta; sb += tb; }
    }
    if (lane == 31) { sbuf[w] = sa; sbuf[32 + w] = sb; }
    __syncthreads();
    if (w == 0 && lane < 16) {
        float wa = sbuf[lane], wb = sbuf[32 + lane];
        #pragma unroll
        for (int o = 1; o < 16; o <<= 1) {
            float ta = __shfl_up_sync(0x0000ffffu, wa, o);
            float tb = __shfl_up_sync(0x0000ffffu, wb, o);
            if (lane >= o) { wa += ta; wb += tb; }
        }
        sbuf[lane] = wa; sbuf[32 + lane] = wb;
    }
    __syncthreads();
    float offa = (w > 0) ? sbuf[w - 1] : 0.f;
    float offb = (w > 0) ? sbuf[32 + w - 1] : 0.f;
    outa[threadIdx.x] = sa + offa;
    outb[threadIdx.x] = sb + offb;
    __syncthreads();
}

__device__ __forceinline__ float inv_cdf_one(const float* c, float tk) {
    // searchsorted left: first j with c[j] >= tk.
    // Range [0,512] has size 513 -> needs exactly 10 halvings.
    int l = 0, h = AA;
    #pragma unroll
    for (int it = 0; it < 10; ++it) {
        if (l < h) {
            int m = (l + h) >> 1;
            if (c[m] < tk) l = m + 1; else h = m;
        }
    }
    int j = min(l, AA - 1);
    float cp = (j > 0) ? c[j - 1] : 0.f;
    float dens = c[j] - cp;
    float p = (float)j + (tk - cp) / fmaxf(dens, 1e-6f);
    return 2.f * p / (float)AA - 1.f;
}

__global__ void __launch_bounds__(512) prep_kernel(const float* __restrict__ attx,
                                                   const float* __restrict__ atty) {
    __shared__ float sbuf[64];
    __shared__ float cx[AA];
    __shared__ float cy[AA];
    int n = blockIdx.x;
    int t = threadIdx.x;

    float ax = attx[n * AA + t];
    float ay = atty[n * AA + t];

    float sax, say;
    blockSum2(ax, ay, sbuf, &sax, &say);
    ax = ax / sax * (float)OUTS;
    ay = ay / say * (float)OUTS;

    const float thr0 = 4.0f * (float)OUTS / (float)AA;  // DENSE*out/A
    #pragma unroll
    for (int it = 0; it < 5; ++it) {
        float mx, my;
        blockMax2(ax, ay, sbuf, &mx, &my);
        float tt = fminf(mx, my);
        if (it == 0) tt = fminf(tt, thr0);
        ax = fminf(ax, tt);
        ay = fminf(ay, tt);
        blockSum2(ax, ay, sbuf, &sax, &say);
        ax += ((float)OUTS - sax) / (float)AA;
        ay += ((float)OUTS - say) / (float)AA;
    }

    blockScan2(ax, ay, cx, cy, sbuf);

    float stepx = cx[AA - 1] / (float)OUTS;
    float stepy = cy[AA - 1] / (float)OUTS;
    float tkx = ((float)t + 0.5f) * stepx;
    float tky = ((float)t + 0.5f) * stepy;

    g_px[n * OUTS + t] = inv_cdf_one(cx, tkx);
    g_py[n * OUTS + t] = inv_cdf_one(cy, tky);
}

__device__ __forceinline__ unsigned int smem_u32(const void* p) {
    unsigned int a;
    asm("{ .reg .u64 t; cvta.to.shared.u64 t, %1; cvt.u32.u64 %0, t; }" : "=r"(a) : "l"(p));
    return a;
}

// one block = one output row. Gathers stay LDG (lanes = consecutive px, coalesced).
// Results staged in SMEM; all GMEM writes done by 4 cp.async.bulk (TMA pipe),
// removing every STG from the LSU/L1 path.
__global__ void __launch_bounds__(512) sample_kernel(const float* __restrict__ data,
                                                     float* __restrict__ out_s,
                                                     float2* __restrict__ out_g) {
    __shared__ float srow[CC][WW];     // 6 KB
    __shared__ float2 sgrid[WW];       // 4 KB

    int j = threadIdx.x;
    int i = blockIdx.x;
    int n = blockIdx.y;

    float py = __ldg(&g_py[n * OUTS + i]);
    float px = __ldg(&g_px[n * OUTS + j]);

    float iy = (py + 1.f) * 0.5f * (float)(HH - 1);
    float fy = floorf(iy);
    float wy = iy - fy;
    int y0 = min(max((int)fy, 0), HH - 1);
    int y1 = min(y0 + 1, HH - 1);
    float omwy = 1.f - wy;

    float ix = (px + 1.f) * 0.5f * (float)(WW - 1);
    float fx = floorf(ix);
    float wx = ix - fx;
    int x0 = min(max((int)fx, 0), WW - 1);
    int x1 = min(x0 + 1, WW - 1);
    float omwx = 1.f - wx;

    const float* img = data + (size_t)n * CC * HH * WW;
    size_t r0 = (size_t)y0 * WW;
    size_t r1 = (size_t)y1 * WW;

    // batch all 12 gathers before combining (MLP)
    float v00[CC], v01[CC], v10[CC], v11[CC];
    #pragma unroll
    for (int c = 0; c < CC; ++c) {
        const float* ch = img + (size_t)c * HH * WW;
        v00[c] = __ldg(ch + r0 + x0);
        v01[c] = __ldg(ch + r0 + x1);
        v10[c] = __ldg(ch + r1 + x0);
        v11[c] = __ldg(ch + r1 + x1);
    }
    #pragma unroll
    for (int c = 0; c < CC; ++c) {
        float top = v00[c] * omwx + v01[c] * wx;
        float bot = v10[c] * omwx + v11[c] * wx;
        srow[c][j] = top * omwy + bot * wy;
    }
    sgrid[j] = make_float2(px, py);
    __syncthreads();

    if (j < 4) {
        asm volatile("fence.proxy.async.shared::cta;" ::: "memory");
        if (j < CC) {
            float* dst = out_s + (((size_t)n * CC + j) * HH + i) * WW;
            unsigned int src = smem_u32(&srow[j][0]);
            asm volatile("cp.async.bulk.global.shared::cta.bulk_group [%0], [%1], %2;"
                         :: "l"(dst), "r"(src), "r"((unsigned int)(WW * 4)) : "memory");
        } else {
            float2* dst = out_g + ((size_t)n * OUTS + i) * OUTS;
            unsigned int src = smem_u32(&sgrid[0]);
            asm volatile("cp.async.bulk.global.shared::cta.bulk_group [%0], [%1], %2;"
                         :: "l"(dst), "r"(src), "r"((unsigned int)(WW * 8)) : "memory");
        }
        asm volatile("cp.async.bulk.commit_group;" ::: "memory");
        // wait until SMEM reads are done so the CTA can safely retire
        asm volatile("cp.async.bulk.wait_group.read 0;" ::: "memory");
    }
}

extern "C" void kernel_launch(void* const* d_in, const int* in_sizes, int n_in,
                              void* d_out, int out_size) {
    const float* data = (const float*)d_in[0];
    const float* attx = (const float*)d_in[1];
    const float* atty = (const float*)d_in[2];

    int N = in_sizes[1] / AA;   // attx is (N, 512, 1)

    float* out = (float*)d_out;
    float* out_s = out;                                        // (N, C, 512, 512)
    float2* out_g = (float2*)(out + (size_t)N * CC * HH * WW); // (N, 512, 512, 2)

    prep_kernel<<<N, 512>>>(attx, atty);
    dim3 grid(OUTS, N);
    sample_kernel<<<grid, 512>>>(data, out_s, out_g);
}

// round 9
// speedup vs baseline: 1.1925x; 1.1925x over previous
#include <cuda_runtime.h>
#include <cstdint>

#define AA 512      // attention length
#define OUTS 512    // out_size
#define HH 512
#define WW 512
#define CC 3
#define NMAX 32
#define RPT 4       // rows per thread

// scratch (allocation-free rule: device globals)
__device__ float g_px[NMAX * OUTS];
__device__ float g_py[NMAX * OUTS];

__device__ __forceinline__ float warpSum(float v) {
    #pragma unroll
    for (int o = 16; o; o >>= 1) v += __shfl_xor_sync(0xffffffffu, v, o);
    return v;
}
__device__ __forceinline__ float warpMax(float v) {
    #pragma unroll
    for (int o = 16; o; o >>= 1) v = fmaxf(v, __shfl_xor_sync(0xffffffffu, v, o));
    return v;
}

// fused block reductions for two values (512 threads), one barrier pair each
__device__ void blockSum2(float a, float b, volatile float* sbuf, float* ra, float* rb) {
    int lane = threadIdx.x & 31, w = threadIdx.x >> 5;
    a = warpSum(a); b = warpSum(b);
    if (lane == 0) { sbuf[w] = a; sbuf[32 + w] = b; }
    __syncthreads();
    if (w == 0) {
        float x = (lane < 16) ? sbuf[lane] : 0.f;
        float y = (lane < 16) ? sbuf[32 + lane] : 0.f;
        x = warpSum(x); y = warpSum(y);
        if (lane == 0) { sbuf[0] = x; sbuf[32] = y; }
    }
    __syncthreads();
    *ra = sbuf[0]; *rb = sbuf[32];
    __syncthreads();
}

__device__ void blockMax2(float a, float b, volatile float* sbuf, float* ra, float* rb) {
    int lane = threadIdx.x & 31, w = threadIdx.x >> 5;
    a = warpMax(a); b = warpMax(b);
    if (lane == 0) { sbuf[w] = a; sbuf[32 + w] = b; }
    __syncthreads();
    if (w == 0) {
        float x = (lane < 16) ? sbuf[lane] : -3.4e38f;
        float y = (lane < 16) ? sbuf[32 + lane] : -3.4e38f;
        x = warpMax(x); y = warpMax(y);
        if (lane == 0) { sbuf[0] = x; sbuf[32] = y; }
    }
    __syncthreads();
    *ra = sbuf[0]; *rb = sbuf[32];
    __syncthreads();
}

// fused inclusive block scan of two 512-value sequences -> outa[tid], outb[tid]
__device__ void blockScan2(float a, float b, float* outa, float* outb, volatile float* sbuf) {
    int lane = threadIdx.x & 31, w = threadIdx.x >> 5;
    float sa = a, sb = b;
    #pragma unroll
    for (int o = 1; o < 32; o <<= 1) {
        float ta = __shfl_up_sync(0xffffffffu, sa, o);
        float tb = __shfl_up_sync(0xffffffffu, sb, o);
        if (lane >= o) { sa += ta; sb += tb; }
    }
    if (lane == 31) { sbuf[w] = sa; sbuf[32 + w] = sb; }
    __syncthreads();
    if (w == 0 && lane < 16) {
        float wa = sbuf[lane], wb = sbuf[32 + lane];
        #pragma unroll
        for (int o = 1; o < 16; o <<= 1) {
            float ta = __shfl_up_sync(0x0000ffffu, wa, o);
            float tb = __shfl_up_sync(0x0000ffffu, wb, o);
            if (lane >= o) { wa += ta; wb += tb; }
        }
        sbuf[lane] = wa; sbuf[32 + lane] = wb;
    }
    __syncthreads();
    float offa = (w > 0) ? sbuf[w - 1] : 0.f;
    float offb = (w > 0) ? sbuf[32 + w - 1] : 0.f;
    outa[threadIdx.x] = sa + offa;
    outb[threadIdx.x] = sb + offb;
    __syncthreads();
}

__device__ __forceinline__ float inv_cdf_one(const float* c, float tk) {
    // searchsorted left: first j with c[j] >= tk.
    // Range [0,512] has size 513 -> needs exactly 10 halvings.
    int l = 0, h = AA;
    #pragma unroll
    for (int it = 0; it < 10; ++it) {
        if (l < h) {
            int m = (l + h) >> 1;
            if (c[m] < tk) l = m + 1; else h = m;
        }
    }
    int j = min(l, AA - 1);
    float cp = (j > 0) ? c[j - 1] : 0.f;
    float dens = c[j] - cp;
    float p = (float)j + (tk - cp) / fmaxf(dens, 1e-6f);
    return 2.f * p / (float)AA - 1.f;
}

__global__ void __launch_bounds__(512) prep_kernel(const float* __restrict__ attx,
                                                   const float* __restrict__ atty) {
    __shared__ float sbuf[64];
    __shared__ float cx[AA];
    __shared__ float cy[AA];
    int n = blockIdx.x;
    int t = threadIdx.x;

    float ax = attx[n * AA + t];
    float ay = atty[n * AA + t];

    float sax, say;
    blockSum2(ax, ay, sbuf, &sax, &say);
    ax = ax / sax * (float)OUTS;
    ay = ay / say * (float)OUTS;

    const float thr0 = 4.0f * (float)OUTS / (float)AA;  // DENSE*out/A
    #pragma unroll
    for (int it = 0; it < 5; ++it) {
        float mx, my;
        blockMax2(ax, ay, sbuf, &mx, &my);
        float tt = fminf(mx, my);
        if (it == 0) tt = fminf(tt, thr0);
        ax = fminf(ax, tt);
        ay = fminf(ay, tt);
        blockSum2(ax, ay, sbuf, &sax, &say);
        ax += ((float)OUTS - sax) / (float)AA;
        ay += ((float)OUTS - say) / (float)AA;
    }

    blockScan2(ax, ay, cx, cy, sbuf);

    float stepx = cx[AA - 1] / (float)OUTS;
    float stepy = cy[AA - 1] / (float)OUTS;
    float tkx = ((float)t + 0.5f) * stepx;
    float tky = ((float)t + 0.5f) * stepy;

    g_px[n * OUTS + t] = inv_cdf_one(cx, tkx);
    g_py[n * OUTS + t] = inv_cdf_one(cy, tky);
}

// Deep-MLP sampler: 128-thread CTAs, each thread owns one px column j and
// RPT=4 consecutive output rows. px coords computed once per thread; all
// 48 gathers issued into registers before any arithmetic consumes them.
// grid: (WW/128 jtiles, OUTS/RPT row tiles, N)
__global__ void __launch_bounds__(128) sample_kernel(const float* __restrict__ data,
                                                     float* __restrict__ out_s,
                                                     float2* __restrict__ out_g) {
    int tx = threadIdx.x;                    // 0..127
    int j = blockIdx.x * 128 + tx;           // output column
    int i0 = blockIdx.y * RPT;               // first output row
    int n = blockIdx.z;

    // px coords (once per thread)
    float px = __ldg(&g_px[n * OUTS + j]);
    float ix = (px + 1.f) * 0.5f * (float)(WW - 1);
    float fx = floorf(ix);
    float wx = ix - fx;
    int x0 = min(max((int)fx, 0), WW - 1);
    int x1 = min(x0 + 1, WW - 1);
    float omwx = 1.f - wx;

    // py coords for RPT rows
    float pyv[RPT], wy[RPT];
    int y0[RPT], y1[RPT];
    #pragma unroll
    for (int r = 0; r < RPT; ++r) {
        float py = __ldg(&g_py[n * OUTS + i0 + r]);
        pyv[r] = py;
        float iy = (py + 1.f) * 0.5f * (float)(HH - 1);
        float fy = floorf(iy);
        wy[r] = iy - fy;
        int yy0 = min(max((int)fy, 0), HH - 1);
        y0[r] = yy0;
        y1[r] = min(yy0 + 1, HH - 1);
    }

    const float* img = data + (size_t)n * CC * HH * WW;

    // batch-issue all 48 gathers before any consumption
    float v00[RPT][CC], v01[RPT][CC], v10[RPT][CC], v11[RPT][CC];
    #pragma unroll
    for (int r = 0; r < RPT; ++r) {
        #pragma unroll
        for (int c = 0; c < CC; ++c) {
            const float* ch = img + (size_t)c * HH * WW;
            const float* r0p = ch + (size_t)y0[r] * WW;
            const float* r1p = ch + (size_t)y1[r] * WW;
            v00[r][c] = __ldg(r0p + x0);
            v01[r][c] = __ldg(r0p + x1);
            v10[r][c] = __ldg(r1p + x0);
            v11[r][c] = __ldg(r1p + x1);
        }
    }

    // combine + store (coalesced: consecutive tx -> consecutive j)
    #pragma unroll
    for (int c = 0; c < CC; ++c) {
        float* o = out_s + (((size_t)n * CC + c) * HH + i0) * WW + j;
        #pragma unroll
        for (int r = 0; r < RPT; ++r) {
            float top = v00[r][c] * omwx + v01[r][c] * wx;
            float bot = v10[r][c] * omwx + v11[r][c] * wx;
            o[(size_t)r * WW] = top * (1.f - wy[r]) + bot * wy[r];
        }
    }

    float2* g = out_g + ((size_t)n * OUTS + i0) * OUTS + j;
    #pragma unroll
    for (int r = 0; r < RPT; ++r)
        g[(size_t)r * OUTS] = make_float2(px, pyv[r]);
}

extern "C" void kernel_launch(void* const* d_in, const int* in_sizes, int n_in,
                              void* d_out, int out_size) {
    const float* data = (const float*)d_in[0];
    const float* attx = (const float*)d_in[1];
    const float* atty = (const float*)d_in[2];

    int N = in_sizes[1] / AA;   // attx is (N, 512, 1)

    float* out = (float*)d_out;
    float* out_s = out;                                        // (N, C, 512, 512)
    float2* out_g = (float2*)(out + (size_t)N * CC * HH * WW); // (N, 512, 512, 2)

    prep_kernel<<<N, 512>>>(attx, atty);
    dim3 block(128);
    dim3 grid(WW / 128, OUTS / RPT, N);
    sample_kernel<<<grid, block>>>(data, out_s, out_g);
}